// round 8
// baseline (speedup 1.0000x reference)
#include <cuda_runtime.h>
#include <cstdint>

// MonarchOutProjection, FUSED single kernel:
//   h2[t][b][n]    = sum_m L[b][n][m] * x[t][m*32+b]
//   out[t][i*32+j] = sum_m R[j][i][m] * h2[t][m][j]
//
// Per 16-token tile: cp.async x into xs[b][m][t] (double-buffered, XOR-swizzled
// t-slots) -> phaseA (warp=b, lane=n, broadcast LDS + reg weights) -> hs[n][b][t]
// -> phaseB (warp=j, lane=i) -> out staged into the warp's own hs plane ->
// coalesced flush. No global intermediate. 512 thr, 1 CTA/SM, ~198KB smem.

#define TILE_T 16
#define XROW 516                   // xs b-stride: 32m*16t + 4
#define XS_FLOATS (32 * XROW)      // 16512
#define HROW 548                   // hs n-plane stride (>= 31*17+15+1, %32==4)
#define HS_FLOATS (32 * HROW)      // 17536
#define SMEM_BYTES ((2 * XS_FLOATS + HS_FLOATS) * 4)   // 202240

__device__ __forceinline__ unsigned smem_addr(const void* p) {
    return (unsigned)__cvta_generic_to_shared(p);
}
__device__ __forceinline__ void cp_async4(unsigned dst, const float* src) {
    asm volatile("cp.async.ca.shared.global [%0], [%1], 4;" :: "r"(dst), "l"(src));
}
__device__ __forceinline__ void cp_commit() {
    asm volatile("cp.async.commit_group;");
}
__device__ __forceinline__ void cp_wait_all() {
    asm volatile("cp.async.wait_group 0;");
}
__device__ __forceinline__ void ffma2(uint64_t& acc, uint64_t a, uint64_t b) {
    asm("fma.rn.f32x2 %0, %1, %2, %0;" : "+l"(acc) : "l"(a), "l"(b));
}
__device__ __forceinline__ uint64_t splat2(float w) {
    uint64_t r;
    asm("mov.b64 %0, {%1, %1};" : "=l"(r) : "f"(w));
    return r;
}

__global__ __launch_bounds__(512, 1)
void monarch_fused(const float* __restrict__ x, const float* __restrict__ L,
                   const float* __restrict__ R, float* __restrict__ out,
                   int ntiles) {
    extern __shared__ float sm[];
    float* hs = sm + 2 * XS_FLOATS;          // hs[n][b][t] : n*548 + b*16 + t
    const int tid  = threadIdx.x;
    const int warp = tid >> 5;               // 0..15
    const int lane = tid & 31;

    const unsigned sbase = smem_addr(sm);

    // Copy mapping: thread = (cb = tid&31, mh = tid>>5); copies m in {mh, mh+16},
    // t = 0..15. dst t-slot XOR-swizzled by (cb>>3) so STS banks are distinct
    // across the {cb, cb+8, cb+16, cb+24} groups that share 4*cb%32.
    const int cb  = tid & 31;
    const int cmh = tid >> 5;
    const int ctsw = 4 * (cb >> 3);

    const int tile0 = blockIdx.x;
    const int tstep = gridDim.x;

    // Prologue: tile0 -> buf0.
    if (tile0 < ntiles) {
        #pragma unroll
        for (int mm = 0; mm < 2; mm++) {
            int m = cmh + 16 * mm;
            const float* src = x + (tile0 * TILE_T) * 1024 + m * 32 + cb;
            unsigned dst = sbase + (cb * XROW + m * 16) * 4;
            #pragma unroll
            for (int t = 0; t < 16; t++)
                cp_async4(dst + (t ^ ctsw) * 4, src + t * 1024);
        }
    }
    cp_commit();

    int cur = 0;
    for (int tile = tile0; tile < ntiles; tile += tstep) {
        cp_wait_all();
        __syncthreads();                     // xs[cur] ready; prev tile done

        // Prefetch next tile into the other buffer (overlaps phaseA/B).
        int nxt = tile + tstep;
        if (nxt < ntiles) {
            unsigned dbase = sbase + (cur ^ 1) * XS_FLOATS * 4;
            #pragma unroll
            for (int mm = 0; mm < 2; mm++) {
                int m = cmh + 16 * mm;
                const float* src = x + (nxt * TILE_T) * 1024 + m * 32 + cb;
                unsigned dst = dbase + (cb * XROW + m * 16) * 4;
                #pragma unroll
                for (int t = 0; t < 16; t++)
                    cp_async4(dst + (t ^ ctsw) * 4, src + t * 1024);
            }
            cp_commit();
        }

        // ---------- Phase A: h2[t][b][n] ----------
        #pragma unroll
        for (int p = 0; p < 2; p++) {
            const int b   = warp + 16 * p;
            const int bsw = b >> 3;          // quad-XOR for xs reads

            float Lreg[32];                  // L[b][n=lane][m]
            const float4* Lp = (const float4*)(L + b * 1024 + lane * 32);
            #pragma unroll
            for (int q = 0; q < 8; q++) {
                float4 v = Lp[q];
                Lreg[4*q+0] = v.x; Lreg[4*q+1] = v.y;
                Lreg[4*q+2] = v.z; Lreg[4*q+3] = v.w;
            }

            uint64_t acc2[8];
            #pragma unroll
            for (int k = 0; k < 8; k++) acc2[k] = 0ull;

            const ulonglong2* xq =
                (const ulonglong2*)(sm + cur * XS_FLOATS) + b * 129;  // XROW/4
            #pragma unroll
            for (int m = 0; m < 32; m++) {
                uint64_t w2 = splat2(Lreg[m]);
                #pragma unroll
                for (int q = 0; q < 4; q++) {
                    ulonglong2 xv = xq[m * 4 + (q ^ bsw)];  // bcast LDS.128, t-quad q
                    ffma2(acc2[2*q+0], w2, xv.x);
                    ffma2(acc2[2*q+1], w2, xv.y);
                }
            }

            // hs[n=lane][b][t] : STS.128 x4 (banks distinct within lane octets)
            float* hp = hs + lane * HROW + b * 16;
            #pragma unroll
            for (int k = 0; k < 4; k++) {
                ulonglong2 v; v.x = acc2[2*k]; v.y = acc2[2*k+1];
                *(ulonglong2*)(hp + 4 * k) = v;
            }
        }
        __syncthreads();                     // all h2 visible

        // ---------- Phase B: out[t][i*32+j] ----------
        #pragma unroll
        for (int p = 0; p < 2; p++) {
            const int j = warp + 16 * p;

            float Rreg[32];                  // R[j][i=lane][m]
            const float4* Rp = (const float4*)(R + j * 1024 + lane * 32);
            #pragma unroll
            for (int q = 0; q < 8; q++) {
                float4 v = Rp[q];
                Rreg[4*q+0] = v.x; Rreg[4*q+1] = v.y;
                Rreg[4*q+2] = v.z; Rreg[4*q+3] = v.w;
            }

            uint64_t acc2[8];
            #pragma unroll
            for (int k = 0; k < 8; k++) acc2[k] = 0ull;

            const ulonglong2* hq = (const ulonglong2*)(hs + j * HROW);
            #pragma unroll
            for (int m = 0; m < 32; m++) {
                uint64_t w2 = splat2(Rreg[m]);
                #pragma unroll
                for (int q = 0; q < 4; q++) {
                    ulonglong2 hv = hq[m * 4 + q];          // bcast LDS.128
                    ffma2(acc2[2*q+0], w2, hv.x);
                    ffma2(acc2[2*q+1], w2, hv.y);
                }
            }
            __syncwarp();                    // plane j reads (this warp only) done

            // Stage output into our own consumed plane:
            // hs[j][i=lane][t'] at j*548 + lane*17 + (t ^ 4*(j>>3)); stride 17
            // -> store conflict-free; XOR makes flush reads conflict-free.
            const int tsw = 4 * (j >> 3);
            float* op = hs + j * HROW + lane * 17;
            #pragma unroll
            for (int k = 0; k < 8; k++) {
                float2 pr; *(uint64_t*)&pr = acc2[k];
                op[(2*k+0) ^ tsw] = pr.x;
                op[(2*k+1) ^ tsw] = pr.y;
            }
        }
        __syncthreads();                     // os staged

        // ---------- Flush: coalesced out writes ----------
        const int t0 = tile * TILE_T;
        #pragma unroll
        for (int e = tid, k = 0; k < 32; e += 512, k++) {
            int jl = e & 31, i2 = (e >> 5) & 31, t = e >> 10;
            out[(t0 + t) * 1024 + i2 * 32 + jl] =
                hs[jl * HROW + i2 * 17 + (t ^ (4 * (jl >> 3)))];
        }
        // hs reuse next tile is fenced by the loop-top __syncthreads.
        cur ^= 1;
    }
}

extern "C" void kernel_launch(void* const* d_in, const int* in_sizes, int n_in,
                              void* d_out, int out_size) {
    const float* x = (const float*)d_in[0];
    const float* L = (const float*)d_in[1];
    const float* R = (const float*)d_in[2];
    float* out = (float*)d_out;

    const int ntok   = in_sizes[0] / 1024;   // 32768
    const int ntiles = ntok / TILE_T;        // 2048

    cudaFuncSetAttribute(monarch_fused,
                         cudaFuncAttributeMaxDynamicSharedMemorySize, SMEM_BYTES);

    int sms = 148;
    cudaDeviceGetAttribute(&sms, cudaDevAttrMultiProcessorCount, 0);

    monarch_fused<<<sms, 512, SMEM_BYTES>>>(x, L, R, out, ntiles);
}

// round 10
// speedup vs baseline: 2.8050x; 2.8050x over previous
#include <cuda_runtime.h>
#include <cstdint>

// MonarchOutProjection:
//   h2[t][b][n]    = sum_m L[b][n][m] * x[t][m*32+b]
//   out[t][i*32+j] = sum_m R[j][i][m] * h2[t][m][j]
//
// R9 = R8 + the missing stage1 end-of-tile __syncthreads (fixes the
// double-buffer race: next tile's cp.async must not overwrite buf[cur^1]
// while slow warps still read it).
//
// R8 design: 2 output rows per thread (lane -> (nh, th); n in {nh, nh+16},
// t in [8*th, 8*th+8)) halves the smem-crossbar replicated-byte cost.
// 256-thread CTAs, 2/SM, 64 weight regs. CTA owns a fixed quarter
// (8 blocks) so weights load once. g_h2 layout [tile][b][n][t].

#define TILE_T 16
#define BROW 516                        // per-block smem row: 32m*16t + 4
#define XS_FLOATS (8 * BROW)            // 4128 (8 blocks per CTA quarter)
#define OS_FLOATS 4608                  // os[t][i][jl]: t*288 + i*9 + jl
#define SMEM1_BYTES (2 * XS_FLOATS * 4)                 // 33024
#define SMEM2_BYTES ((2 * XS_FLOATS + OS_FLOATS) * 4)   // 51456

// g_h2[tile][b][n][t] : idx = tile*16384 + b*512 + n*16 + t
__device__ float g_h2[33554432];

__device__ __forceinline__ unsigned smem_addr(const void* p) {
    return (unsigned)__cvta_generic_to_shared(p);
}
__device__ __forceinline__ void cp_async4(unsigned dst, const float* src) {
    asm volatile("cp.async.ca.shared.global [%0], [%1], 4;" :: "r"(dst), "l"(src));
}
__device__ __forceinline__ void cp_async16(unsigned dst, const float* src) {
    asm volatile("cp.async.cg.shared.global [%0], [%1], 16;" :: "r"(dst), "l"(src));
}
__device__ __forceinline__ void cp_commit() {
    asm volatile("cp.async.commit_group;");
}
__device__ __forceinline__ void cp_wait1() {
    asm volatile("cp.async.wait_group 1;");
}
__device__ __forceinline__ void ffma2(uint64_t& acc, uint64_t a, uint64_t b) {
    asm("fma.rn.f32x2 %0, %1, %2, %0;" : "+l"(acc) : "l"(a), "l"(b));
}
__device__ __forceinline__ uint64_t splat2(float w) {
    uint64_t r;
    asm("mov.b64 %0, {%1, %1};" : "=l"(r) : "f"(w));
    return r;
}

__global__ __launch_bounds__(256, 2)
void monarch_stage1(const float* __restrict__ x, const float* __restrict__ L,
                    int ntiles) {
    extern __shared__ float sm[];        // buf0|buf1 : xs[bl][m][t], row BROW
    const int tid  = threadIdx.x;
    const int warp = tid >> 5;           // bl in [0,8)
    const int lane = tid & 31;
    const int nh = lane & 15, th = lane >> 4;
    const int q  = blockIdx.x & 3;       // quarter: blocks [8q, 8q+8)
    const int b  = 8 * q + warp;

    // Weights (once): Lr[r][m] = L[b][nh + 16r][m]  (64 regs)
    float Lr[2][32];
    #pragma unroll
    for (int r = 0; r < 2; r++) {
        const float4* Lp = (const float4*)(L + b * 1024 + (nh + 16 * r) * 32);
        #pragma unroll
        for (int g = 0; g < 8; g++) {
            float4 v = Lp[g];
            Lr[r][4*g+0] = v.x; Lr[r][4*g+1] = v.y;
            Lr[r][4*g+2] = v.z; Lr[r][4*g+3] = v.w;
        }
    }

    const unsigned sbase = smem_addr(sm);
    const int tstep = gridDim.x >> 2;
    const int tile0 = blockIdx.x >> 2;

    // Fill mapping: thread = (cbl = tid&7, cm = tid>>3), 16 t-values, 4B each.
    const int cbl = tid & 7, cm = tid >> 3;

    if (tile0 < ntiles) {
        const float* src = x + (tile0 * TILE_T) * 1024 + cm * 32 + 8 * q + cbl;
        unsigned dst = sbase + (cbl * BROW + cm * 16) * 4;
        #pragma unroll
        for (int t = 0; t < 16; t++)
            cp_async4(dst + t * 4, src + t * 1024);
    }
    cp_commit();

    int cur = 0;
    for (int tile = tile0; tile < ntiles; tile += tstep) {
        int nxt = tile + tstep;
        if (nxt < ntiles) {
            const float* src = x + (nxt * TILE_T) * 1024 + cm * 32 + 8 * q + cbl;
            unsigned dst = sbase + ((cur ^ 1) * XS_FLOATS + cbl * BROW + cm * 16) * 4;
            #pragma unroll
            for (int t = 0; t < 16; t++)
                cp_async4(dst + t * 4, src + t * 1024);
        }
        cp_commit();
        cp_wait1();
        __syncthreads();

        // acc[r][p] (u64) covers n = nh+16r, t = 8*th + 2p, 2p+1
        uint64_t acc[2][4];
        #pragma unroll
        for (int r = 0; r < 2; r++)
            #pragma unroll
            for (int p = 0; p < 4; p++) acc[r][p] = 0ull;

        const float* xw = sm + cur * XS_FLOATS + warp * BROW;
        #pragma unroll
        for (int m = 0; m < 32; m++) {
            const ulonglong2* xq = (const ulonglong2*)(xw + m * 16);
            ulonglong2 xv0 = xq[2 * th];         // t = 8th+0..3 (2 addrs/warp)
            ulonglong2 xv1 = xq[2 * th + 1];     // t = 8th+4..7
            uint64_t w0 = splat2(Lr[0][m]);
            uint64_t w1 = splat2(Lr[1][m]);
            ffma2(acc[0][0], w0, xv0.x); ffma2(acc[0][1], w0, xv0.y);
            ffma2(acc[0][2], w0, xv1.x); ffma2(acc[0][3], w0, xv1.y);
            ffma2(acc[1][0], w1, xv0.x); ffma2(acc[1][1], w1, xv0.y);
            ffma2(acc[1][2], w1, xv1.x); ffma2(acc[1][3], w1, xv1.y);
        }

        // Store: g_h2[tile][b][n][t]; per instr warp spans ~512B (near-coalesced).
        float* gp = g_h2 + tile * 16384 + b * 512 + th * 8;
        #pragma unroll
        for (int r = 0; r < 2; r++) {
            float* rp = gp + (nh + 16 * r) * 16;
            ulonglong2 v0; v0.x = acc[r][0]; v0.y = acc[r][1];
            ulonglong2 v1; v1.x = acc[r][2]; v1.y = acc[r][3];
            *(ulonglong2*)(rp)     = v0;     // t = 8th+0..3
            *(ulonglong2*)(rp + 4) = v1;     // t = 8th+4..7
        }

        // RACE FIX: all warps must finish reading buf[cur] before any thread
        // enters the next iteration and cp.asyncs into buf[cur^1] (which the
        // *previous* iteration read) -- and more importantly before the next
        // iteration's issue targets THIS buffer two iterations later.
        __syncthreads();

        cur ^= 1;
    }
}

__global__ __launch_bounds__(256, 2)
void monarch_stage2(const float* __restrict__ R, float* __restrict__ out,
                    int ntiles) {
    extern __shared__ float sm[];        // buf0|buf1 : hs[jl][m][t] ; then os
    float* os = sm + 2 * XS_FLOATS;      // os[t][i][jl] : t*288 + i*9 + jl
    const int tid  = threadIdx.x;
    const int warp = tid >> 5;           // jl in [0,8)
    const int lane = tid & 31;
    const int nh = lane & 15, th = lane >> 4;
    const int q  = blockIdx.x & 3;       // quarter: j in [8q, 8q+8)
    const int j  = 8 * q + warp;
    const int ws = warp & 3;             // hs quad XOR key

    // Weights (once): Rr[r][m] = R[j][nh + 16r][m]
    float Rr[2][32];
    #pragma unroll
    for (int r = 0; r < 2; r++) {
        const float4* Rp = (const float4*)(R + j * 1024 + (nh + 16 * r) * 32);
        #pragma unroll
        for (int g = 0; g < 8; g++) {
            float4 v = Rp[g];
            Rr[r][4*g+0] = v.x; Rr[r][4*g+1] = v.y;
            Rr[r][4*g+2] = v.z; Rr[r][4*g+3] = v.w;
        }
    }

    const unsigned sbase = smem_addr(sm);
    const int tstep = gridDim.x >> 2;
    const int tile0 = blockIdx.x >> 2;

    // Fill: hs[jl][m][t-quad] = g_h2[tile][m][j][t], XOR-swizzled quad slots.
    const int ctq = tid & 3, cjl = (tid >> 2) & 7;

    if (tile0 < ntiles) {
        #pragma unroll
        for (int k = 0; k < 4; k++) {
            int m = (tid >> 5) + k * 8;
            const float* src = g_h2 + tile0 * 16384 + m * 512 + (8 * q + cjl) * 16 + ctq * 4;
            unsigned dst = sbase + (cjl * BROW + m * 16 + (ctq ^ (cjl & 3)) * 4) * 4;
            cp_async16(dst, src);
        }
    }
    cp_commit();

    int cur = 0;
    for (int tile = tile0; tile < ntiles; tile += tstep) {
        int nxt = tile + tstep;
        if (nxt < ntiles) {
            #pragma unroll
            for (int k = 0; k < 4; k++) {
                int m = (tid >> 5) + k * 8;
                const float* src = g_h2 + nxt * 16384 + m * 512 + (8 * q + cjl) * 16 + ctq * 4;
                unsigned dst = sbase + ((cur ^ 1) * XS_FLOATS
                               + cjl * BROW + m * 16 + (ctq ^ (cjl & 3)) * 4) * 4;
                cp_async16(dst, src);
            }
        }
        cp_commit();
        cp_wait1();
        __syncthreads();                 // hs[cur] ready; prev os flush done

        uint64_t acc[2][4];
        #pragma unroll
        for (int r = 0; r < 2; r++)
            #pragma unroll
            for (int p = 0; p < 4; p++) acc[r][p] = 0ull;

        const float* hw = sm + cur * XS_FLOATS + warp * BROW;
        #pragma unroll
        for (int m = 0; m < 32; m++) {
            const ulonglong2* hq = (const ulonglong2*)(hw + m * 16);
            ulonglong2 hv0 = hq[(2 * th)     ^ ws];
            ulonglong2 hv1 = hq[(2 * th + 1) ^ ws];
            uint64_t w0 = splat2(Rr[0][m]);
            uint64_t w1 = splat2(Rr[1][m]);
            ffma2(acc[0][0], w0, hv0.x); ffma2(acc[0][1], w0, hv0.y);
            ffma2(acc[0][2], w0, hv1.x); ffma2(acc[0][3], w0, hv1.y);
            ffma2(acc[1][0], w1, hv0.x); ffma2(acc[1][1], w1, hv0.y);
            ffma2(acc[1][2], w1, hv1.x); ffma2(acc[1][3], w1, hv1.y);
        }

        // Stage to os[t][i][jl]; this barrier also fences hs[cur] reads
        // against the next iteration's cp.async refill of hs[cur^1].
        #pragma unroll
        for (int r = 0; r < 2; r++) {
            float* op = os + (nh + 16 * r) * 9 + warp;
            #pragma unroll
            for (int p = 0; p < 4; p++) {
                float2 pr; *(uint64_t*)&pr = acc[r][p];
                op[(8 * th + 2 * p + 0) * 288] = pr.x;
                op[(8 * th + 2 * p + 1) * 288] = pr.y;
            }
        }
        __syncthreads();

        // Coalesced flush: out[t][i*32 + 8q + jl].
        const int t0 = tile * TILE_T;
        #pragma unroll
        for (int k = 0; k < 16; k++) {
            int e = tid + k * 256;
            int jl = e & 7, i2 = (e >> 3) & 31, t = e >> 8;
            out[(t0 + t) * 1024 + i2 * 32 + 8 * q + jl] = os[t * 288 + i2 * 9 + jl];
        }
        // os reuse next tile fenced by loop-top __syncthreads.
        cur ^= 1;
    }
}

extern "C" void kernel_launch(void* const* d_in, const int* in_sizes, int n_in,
                              void* d_out, int out_size) {
    const float* x = (const float*)d_in[0];
    const float* L = (const float*)d_in[1];
    const float* R = (const float*)d_in[2];
    float* out = (float*)d_out;

    const int ntok   = in_sizes[0] / 1024;   // 32768
    const int ntiles = ntok / TILE_T;        // 2048

    cudaFuncSetAttribute(monarch_stage1,
                         cudaFuncAttributeMaxDynamicSharedMemorySize, SMEM1_BYTES);
    cudaFuncSetAttribute(monarch_stage2,
                         cudaFuncAttributeMaxDynamicSharedMemorySize, SMEM2_BYTES);

    int sms = 148;
    cudaDeviceGetAttribute(&sms, cudaDevAttrMultiProcessorCount, 0);
    int grid = 4 * ((2 * sms) / 4);          // multiple of 4 quarters, 2 CTAs/SM

    monarch_stage1<<<grid, 256, SMEM1_BYTES>>>(x, L, ntiles);
    monarch_stage2<<<grid, 256, SMEM2_BYTES>>>(R, out, ntiles);
}